// round 1
// baseline (speedup 1.0000x reference)
#include <cuda_runtime.h>

#define W_IMG 128
#define H_IMG 128
#define C_IN  64
#define OC    64
#define KNPTS 9
#define PIX   32          // pixels per block
#define CC    8           // channels per K-chunk
#define KCHUNK (CC*KNPTS) // 72
#define NCHUNK (C_IN/CC)  // 8
#define SROW  76          // padded smem row length (floats); 76*4 bytes is 16B-aligned
#define THREADS 256
#define PLANE (H_IMG*W_IMG)   // 16384
#define KTOT  (C_IN*KNPTS)    // 576

struct InterpItem { int i00, i01, i10, i11; float w00, w01, w10, w11; };

__global__ __launch_bounds__(THREADS)
void dcn_fp32_kernel(const float* __restrict__ x,
                     const float* __restrict__ offset,
                     const float* __restrict__ weight,
                     float* __restrict__ out)
{
    __shared__ InterpItem interp[KNPTS * PIX];   // 288 * 32B  = 9216 B
    __shared__ float s[PIX * SROW];              // 32*76*4    = 9728 B
    __shared__ float wsh[OC * SROW];             // 64*76*4    = 19456 B

    const int b   = blockIdx.x;
    const int n   = b >> 9;            // 512 blocks per image
    const int pixbase = (b & 511) * PIX;
    const int tid = threadIdx.x;

    const float* xn   = x + (size_t)n * C_IN * PLANE;
    const float* offn = offset + (size_t)n * (KNPTS * 2) * PLANE;

    // ---- Phase 1: build interpolation table (per kernel-point, per pixel) ----
    for (int it = tid; it < KNPTS * PIX; it += THREADS) {
        const int kn = it >> 5;      // /PIX
        const int p  = it & 31;
        const int pix = pixbase + p;
        const int oh = pix >> 7, ow = pix & 127;
        // iy = oh + off_y, ix = ow + off_x (normalized-grid round trip collapses)
        const float offy = offn[(kn * 2 + 0) * PLANE + pix];
        const float offx = offn[(kn * 2 + 1) * PLANE + pix];
        const float iy = (float)oh + offy;
        const float ix = (float)ow + offx;
        const float y0f = floorf(iy), x0f = floorf(ix);
        const float wy1 = iy - y0f,  wx1 = ix - x0f;
        const float wy0 = 1.f - wy1, wx0 = 1.f - wx1;
        const int x0 = (int)x0f, y0 = (int)y0f;
        const int x1 = x0 + 1,  y1 = y0 + 1;
        const float mx0 = (x0 >= 0 && x0 <= W_IMG - 1) ? 1.f : 0.f;
        const float mx1 = (x1 >= 0 && x1 <= W_IMG - 1) ? 1.f : 0.f;
        const float my0 = (y0 >= 0 && y0 <= H_IMG - 1) ? 1.f : 0.f;
        const float my1 = (y1 >= 0 && y1 <= H_IMG - 1) ? 1.f : 0.f;
        const int cx0 = min(max(x0, 0), W_IMG - 1);
        const int cx1 = min(max(x1, 0), W_IMG - 1);
        const int cy0 = min(max(y0, 0), H_IMG - 1);
        const int cy1 = min(max(y1, 0), H_IMG - 1);
        InterpItem t;
        t.i00 = cy0 * W_IMG + cx0;  t.i01 = cy0 * W_IMG + cx1;
        t.i10 = cy1 * W_IMG + cx0;  t.i11 = cy1 * W_IMG + cx1;
        t.w00 = wx0 * wy0 * mx0 * my0;
        t.w01 = wx1 * wy0 * mx1 * my0;
        t.w10 = wx0 * wy1 * mx0 * my1;
        t.w11 = wx1 * wy1 * mx1 * my1;
        interp[it] = t;
    }

    float acc[8];
#pragma unroll
    for (int j = 0; j < 8; j++) acc[j] = 0.f;

    const int ocg = tid & 7;     // oc = ocg + j*8 (strided: conflict-free wsh reads)
    const int p   = tid >> 3;    // pixel within the block tile

    for (int ch = 0; ch < NCHUNK; ch++) {
        const int c0 = ch * CC;
        const int k0 = c0 * KNPTS;
        __syncthreads();

        // ---- fill sampled tile s[pixel][ck], ck = c_local*9 + kn ----
        for (int it = tid; it < KCHUNK * PIX; it += THREADS) {
            const int ck = it >> 5;
            const int pp = it & 31;
            const int cl = ck / KNPTS;
            const int kn = ck - cl * KNPTS;
            const InterpItem t = interp[kn * PIX + pp];
            const float* xc = xn + (c0 + cl) * PLANE;
            const float v = xc[t.i00] * t.w00 + xc[t.i01] * t.w01
                          + xc[t.i10] * t.w10 + xc[t.i11] * t.w11;
            s[pp * SROW + ck] = v;
        }
        // ---- stage weight chunk wsh[oc][kk] (global (c,kn) minor order is contiguous) ----
        for (int it = tid; it < OC * KCHUNK; it += THREADS) {
            const int oc = it / KCHUNK;
            const int kk = it - oc * KCHUNK;
            wsh[oc * SROW + kk] = weight[oc * KTOT + k0 + kk];
        }
        __syncthreads();

        // ---- rank-KCHUNK update, float4 vectorized ----
        const float* srow = s + p * SROW;
#pragma unroll
        for (int kk = 0; kk < KCHUNK; kk += 4) {
            const float4 sv = *(const float4*)(srow + kk);
#pragma unroll
            for (int j = 0; j < 8; j++) {
                const float4 wv = *(const float4*)(wsh + (ocg + j * 8) * SROW + kk);
                acc[j] += sv.x * wv.x + sv.y * wv.y + sv.z * wv.z + sv.w * wv.w;
            }
        }
    }

    // ---- write out[n][oc][pix] ----
#pragma unroll
    for (int j = 0; j < 8; j++) {
        const int oc = ocg + j * 8;
        out[((size_t)n * OC + oc) * PLANE + pixbase + p] = acc[j];
    }
}

extern "C" void kernel_launch(void* const* d_in, const int* in_sizes, int n_in,
                              void* d_out, int out_size)
{
    const float* x      = (const float*)d_in[0];   // (4, 64, 128, 128)
    const float* offset = (const float*)d_in[1];   // (4, 18, 128, 128)
    const float* weight = (const float*)d_in[2];   // (64, 64, 9)
    float* out = (float*)d_out;                    // (4, 64, 128, 128)
    (void)in_sizes; (void)n_in; (void)out_size;

    const int nblocks = 4 * (PLANE / PIX);         // 4 * 512 = 2048
    dcn_fp32_kernel<<<nblocks, THREADS>>>(x, offset, weight, out);
}

// round 2
// speedup vs baseline: 1.8420x; 1.8420x over previous
#include <cuda_runtime.h>

#define W_IMG 128
#define H_IMG 128
#define C_IN  64
#define OC    64
#define KNPTS 9
#define PLANE 16384
#define KTOT  576

#define PIX    64         // pixels per block
#define CC     8          // channels per K-chunk
#define KCHUNK 72         // CC * KNPTS
#define NCHUNK 8          // C_IN / CC
#define SROW   76         // padded s-row (floats): 304B stride -> order-8 bank walk
#define THREADS 128

// NHWC scratch for x (harness forbids allocation; static __device__ is the sanctioned path)
__device__ float g_xhwc[(size_t)4 * PLANE * C_IN];

// ---------------- NCHW -> NHWC transpose ----------------
__global__ __launch_bounds__(256)
void nchw_to_nhwc_kernel(const float* __restrict__ x)
{
    __shared__ float t[64][33];
    const int n   = blockIdx.x >> 9;            // 512 tiles per image
    const int hw0 = (blockIdx.x & 511) << 5;    // 32 pixels per tile
    const int tid = threadIdx.x;
    const float* xn = x + ((size_t)n << 20);    // n * 64 * 16384
    for (int idx = tid; idx < 64 * 32; idx += 256) {
        const int c = idx >> 5, i = idx & 31;
        t[c][i] = xn[((size_t)c << 14) + hw0 + i];   // coalesced 128B per warp
    }
    __syncthreads();
    float* dst = g_xhwc + (((size_t)n << 14) + hw0) * 64;
    for (int idx = tid; idx < 64 * 32; idx += 256) {
        const int i = idx >> 6, c = idx & 63;
        dst[(size_t)i * 64 + c] = t[c][i];           // coalesced 256B per pixel
    }
}

// ---------------- main deformable-conv kernel ----------------
struct Interp { short x0, y0; float fx, fy; };      // 12 bytes

__global__ __launch_bounds__(THREADS, 4)
void dcn_main_kernel(const float* __restrict__ offset,
                     const float* __restrict__ weight,
                     float* __restrict__ out)
{
    __shared__ Interp interp[PIX * KNPTS];   // 576 * 12 = 6912 B
    __shared__ float  s[PIX * SROW];         // 19456 B
    __shared__ float  wsh[OC * KCHUNK];      // 18432 B  (total 44800 B)

    const int b       = blockIdx.x;
    const int n       = b >> 8;              // 256 blocks per image
    const int pixbase = (b & 255) << 6;      // 64 consecutive pixels (half a row)
    const int tid     = threadIdx.x;

    const float* offn = offset + (size_t)n * (KNPTS * 2) * PLANE;
    const float* xb   = g_xhwc + ((size_t)n << 14) * 64;

    // ---- Phase 1: per-pixel/kernel-point interp metadata ----
    for (int it = tid; it < PIX * KNPTS; it += THREADS) {
        const int p  = it / 9;
        const int kn = it - p * 9;
        const int pix = pixbase + p;
        const int oh = pix >> 7, ow = pix & 127;
        const float iy = (float)oh + offn[(2 * kn)     * PLANE + pix];
        const float ix = (float)ow + offn[(2 * kn + 1) * PLANE + pix];
        const float y0f = floorf(iy), x0f = floorf(ix);
        Interp t;
        t.x0 = (short)x0f; t.y0 = (short)y0f;
        t.fx = ix - x0f;   t.fy = iy - y0f;
        interp[it] = t;
    }

    float acc[4][8];
#pragma unroll
    for (int i = 0; i < 4; i++)
#pragma unroll
        for (int j = 0; j < 8; j++) acc[i][j] = 0.f;

    const int pg  = tid & 15;    // pixel group: owns pixels pg + 16*i
    const int ocg = tid >> 4;    // oc group:  owns ocs   ocg*8 + j

    for (int ch = 0; ch < NCHUNK; ch++) {
        const int c0 = ch * CC;
        __syncthreads();

        // ---- sample 8 channels per (pixel, kn) from NHWC via LDG.128 ----
        for (int it = tid; it < PIX * KNPTS; it += THREADS) {
            const int p  = it / 9;
            const int kn = it - p * 9;
            const Interp t = interp[it];
            const int x0 = t.x0, y0 = t.y0, x1 = x0 + 1, y1 = y0 + 1;
            const float wx1 = t.fx, wy1 = t.fy;
            const float wx0 = 1.f - wx1, wy0 = 1.f - wy1;
            const float mx0 = ((unsigned)x0 < 128u) ? 1.f : 0.f;
            const float mx1 = ((unsigned)x1 < 128u) ? 1.f : 0.f;
            const float my0 = ((unsigned)y0 < 128u) ? 1.f : 0.f;
            const float my1 = ((unsigned)y1 < 128u) ? 1.f : 0.f;
            const int cx0 = min(max(x0, 0), 127), cx1 = min(max(x1, 0), 127);
            const int cy0 = min(max(y0, 0), 127), cy1 = min(max(y1, 0), 127);
            const float w00 = wx0 * wy0 * mx0 * my0;
            const float w01 = wx1 * wy0 * mx1 * my0;
            const float w10 = wx0 * wy1 * mx0 * my1;
            const float w11 = wx1 * wy1 * mx1 * my1;
            const float* t00 = xb + (((cy0 << 7) + cx0) << 6) + c0;
            const float* t01 = xb + (((cy0 << 7) + cx1) << 6) + c0;
            const float* t10 = xb + (((cy1 << 7) + cx0) << 6) + c0;
            const float* t11 = xb + (((cy1 << 7) + cx1) << 6) + c0;
            float v[8];
            {
                const float4 a = *(const float4*)t00;
                const float4 bb = *(const float4*)(t00 + 4);
                v[0] = w00 * a.x;  v[1] = w00 * a.y;  v[2] = w00 * a.z;  v[3] = w00 * a.w;
                v[4] = w00 * bb.x; v[5] = w00 * bb.y; v[6] = w00 * bb.z; v[7] = w00 * bb.w;
            }
            {
                const float4 a = *(const float4*)t01;
                const float4 bb = *(const float4*)(t01 + 4);
                v[0] += w01 * a.x;  v[1] += w01 * a.y;  v[2] += w01 * a.z;  v[3] += w01 * a.w;
                v[4] += w01 * bb.x; v[5] += w01 * bb.y; v[6] += w01 * bb.z; v[7] += w01 * bb.w;
            }
            {
                const float4 a = *(const float4*)t10;
                const float4 bb = *(const float4*)(t10 + 4);
                v[0] += w10 * a.x;  v[1] += w10 * a.y;  v[2] += w10 * a.z;  v[3] += w10 * a.w;
                v[4] += w10 * bb.x; v[5] += w10 * bb.y; v[6] += w10 * bb.z; v[7] += w10 * bb.w;
            }
            {
                const float4 a = *(const float4*)t11;
                const float4 bb = *(const float4*)(t11 + 4);
                v[0] += w11 * a.x;  v[1] += w11 * a.y;  v[2] += w11 * a.z;  v[3] += w11 * a.w;
                v[4] += w11 * bb.x; v[5] += w11 * bb.y; v[6] += w11 * bb.z; v[7] += w11 * bb.w;
            }
            float* sp = s + p * SROW + kn;     // ck = cl*9 + kn (matches weight minor order)
#pragma unroll
            for (int cl = 0; cl < 8; cl++) sp[cl * 9] = v[cl];
        }

        // ---- stage weight chunk contiguously (float4) ----
        for (int idx = tid; idx < OC * KCHUNK / 4; idx += THREADS) {
            const int oc = idx / (KCHUNK / 4);
            const int kq = idx - oc * (KCHUNK / 4);
            ((float4*)wsh)[oc * (KCHUNK / 4) + kq] =
                ((const float4*)(weight + oc * KTOT + ch * KCHUNK))[kq];
        }
        __syncthreads();

        // ---- register-tiled rank-72 update: 4 pixels x 8 ocs per thread ----
#pragma unroll
        for (int kq = 0; kq < KCHUNK / 4; kq++) {
            float4 sv[4];
#pragma unroll
            for (int i = 0; i < 4; i++)
                sv[i] = *(const float4*)(s + (pg + 16 * i) * SROW + kq * 4);
#pragma unroll
            for (int j = 0; j < 8; j++) {
                const float4 wv = *(const float4*)(wsh + (ocg * 8 + j) * KCHUNK + kq * 4);
#pragma unroll
                for (int i = 0; i < 4; i++)
                    acc[i][j] += sv[i].x * wv.x + sv[i].y * wv.y
                               + sv[i].z * wv.z + sv[i].w * wv.w;
            }
        }
    }

    // ---- write out[n][oc][pix] ----
#pragma unroll
    for (int j = 0; j < 8; j++) {
        const int oc = ocg * 8 + j;
        float* op = out + (((size_t)n * OC + oc) << 14) + pixbase + pg;
#pragma unroll
        for (int i = 0; i < 4; i++) op[16 * i] = acc[i][j];
    }
}

extern "C" void kernel_launch(void* const* d_in, const int* in_sizes, int n_in,
                              void* d_out, int out_size)
{
    const float* x      = (const float*)d_in[0];   // (4, 64, 128, 128)
    const float* offset = (const float*)d_in[1];   // (4, 18, 128, 128)
    const float* weight = (const float*)d_in[2];   // (64, 64, 9)
    float* out = (float*)d_out;                    // (4, 64, 128, 128)
    (void)in_sizes; (void)n_in; (void)out_size;

    nchw_to_nhwc_kernel<<<4 * 512, 256>>>(x);
    dcn_main_kernel<<<4 * 256, THREADS>>>(offset, weight, out);
}

// round 4
// speedup vs baseline: 3.0234x; 1.6413x over previous
#include <cuda_runtime.h>

#define C_IN  64
#define OC    64
#define KNPTS 9
#define PLANE 16384
#define KTOT  576

#define PIX    64        // pixels per block
#define THREADS 128
#define SROWQ  16        // float4 units per s row (64 floats = 256B, XOR-swizzled)

// scratch (allocation is forbidden; __device__ globals are the sanctioned path)
__device__ float g_xhwc[(size_t)4 * PLANE * C_IN];   // NHWC x
__device__ float g_wperm[OC * KTOT];                 // weight permuted to k' = kn*64 + c

// ---------------- NCHW -> NHWC transpose ----------------
__global__ __launch_bounds__(256)
void nchw_to_nhwc_kernel(const float* __restrict__ x)
{
    __shared__ float t[64][33];
    const int n   = blockIdx.x >> 9;
    const int hw0 = (blockIdx.x & 511) << 5;
    const int tid = threadIdx.x;
    const float* xn = x + ((size_t)n << 20);
    for (int idx = tid; idx < 64 * 32; idx += 256) {
        const int c = idx >> 5, i = idx & 31;
        t[c][i] = xn[((size_t)c << 14) + hw0 + i];
    }
    __syncthreads();
    float* dst = g_xhwc + (((size_t)n << 14) + hw0) * 64;
    for (int idx = tid; idx < 64 * 32; idx += 256) {
        const int i = idx >> 6, c = idx & 63;
        dst[(size_t)i * 64 + c] = t[c][i];
    }
}

// ---------------- weight permutation: k = c*9+kn  ->  k' = kn*64+c ----------------
__global__ __launch_bounds__(256)
void permute_w_kernel(const float* __restrict__ w)
{
    const int i = blockIdx.x * 256 + threadIdx.x;
    if (i < OC * KTOT) {
        const int oc = i / KTOT, k = i - oc * KTOT;
        const int kn = k >> 6, c = k & 63;
        g_wperm[i] = w[oc * KTOT + c * KNPTS + kn];
    }
}

// ---------------- main deformable-conv kernel ----------------
struct Interp { short x0, y0; float fx, fy; };   // 12 bytes

__global__ __launch_bounds__(THREADS, 3)
void dcn_main_kernel(const float* __restrict__ offset, float* __restrict__ out)
{
    __shared__ Interp interp[PIX * KNPTS];       // 6912 B
    __shared__ float4 s4[PIX * SROWQ];           // 16384 B (XOR-swizzled sampled tile)
    __shared__ float  wsh[OC * 64];              // 16384 B (one kn-chunk of weights)

    const int b       = blockIdx.x;
    const int n       = b >> 8;                  // 256 blocks per image
    const int pixbase = (b & 255) << 6;          // 64 consecutive pixels
    const int tid     = threadIdx.x;
    const int lane    = tid & 31;
    const int warp    = tid >> 5;
    const int half    = lane >> 4;               // which task in the warp
    const int lh      = lane & 15;               // lane-in-half: owns channels 4lh..4lh+3

    const float* offn = offset + (size_t)n * (KNPTS * 2) * PLANE;
    const float* xb   = g_xhwc + (((size_t)n) << 14) * 64;

    // ---- Phase 1: interp metadata per (pixel, kernel-point) ----
    for (int it = tid; it < PIX * KNPTS; it += THREADS) {
        const int p  = it / 9;
        const int kn = it - p * 9;
        const int pix = pixbase + p;
        const int oh = pix >> 7, ow = pix & 127;
        const float iy = (float)oh + offn[(2 * kn)     * PLANE + pix];
        const float ix = (float)ow + offn[(2 * kn + 1) * PLANE + pix];
        const float y0f = floorf(iy), x0f = floorf(ix);
        Interp t;
        t.x0 = (short)x0f; t.y0 = (short)y0f;
        t.fx = ix - x0f;   t.fy = iy - y0f;
        interp[it] = t;
    }

    // packed accumulators: (even-k, odd-k) partial sums
    unsigned long long acc2[4][8];
#pragma unroll
    for (int i = 0; i < 4; i++)
#pragma unroll
        for (int j = 0; j < 8; j++) acc2[i][j] = 0ull;

    const int pg  = tid & 15;    // pixel group (GEMM): owns pixels pg + 16*i
    const int ocg = tid >> 4;    // oc group: owns ocs ocg*8 + j

    for (int kn = 0; kn < KNPTS; kn++) {
        __syncthreads();   // also orders phase-1 interp writes before first use

        // ---- sampling: 2 tasks per warp, lane-per-channel-quad, all 64 ch at once ----
#pragma unroll
        for (int it = 0; it < 8; it++) {
            const int p = it * 8 + warp * 2 + half;   // pixel within tile
            const Interp t = interp[p * 9 + kn];
            const int x0 = t.x0, y0 = t.y0, x1 = x0 + 1, y1 = y0 + 1;
            const float wx1 = t.fx, wy1 = t.fy;
            const float wx0 = 1.f - wx1, wy0 = 1.f - wy1;
            const float mx0 = ((unsigned)x0 < 128u) ? 1.f : 0.f;
            const float mx1 = ((unsigned)x1 < 128u) ? 1.f : 0.f;
            const float my0 = ((unsigned)y0 < 128u) ? 1.f : 0.f;
            const float my1 = ((unsigned)y1 < 128u) ? 1.f : 0.f;
            const int cx0 = min(max(x0, 0), 127), cx1 = min(max(x1, 0), 127);
            const int cy0 = min(max(y0, 0), 127), cy1 = min(max(y1, 0), 127);
            const float w00 = wx0 * wy0 * mx0 * my0;
            const float w01 = wx1 * wy0 * mx1 * my0;
            const float w10 = wx0 * wy1 * mx0 * my1;
            const float w11 = wx1 * wy1 * mx1 * my1;
            // each tap: 256B coalesced across the 16-lane half-warp
            const float4 a = *(const float4*)(xb + (((cy0 << 7) + cx0) << 6) + 4 * lh);
            const float4 bb= *(const float4*)(xb + (((cy0 << 7) + cx1) << 6) + 4 * lh);
            const float4 c = *(const float4*)(xb + (((cy1 << 7) + cx0) << 6) + 4 * lh);
            const float4 d = *(const float4*)(xb + (((cy1 << 7) + cx1) << 6) + 4 * lh);
            float4 v;
            v.x = w00 * a.x + w01 * bb.x + w10 * c.x + w11 * d.x;
            v.y = w00 * a.y + w01 * bb.y + w10 * c.y + w11 * d.y;
            v.z = w00 * a.z + w01 * bb.z + w10 * c.z + w11 * d.z;
            v.w = w00 * a.w + w01 * bb.w + w10 * c.w + w11 * d.w;
            s4[p * SROWQ + (lh ^ (p & 15))] = v;      // XOR swizzle, STS.128
        }

        // ---- stage this kn-chunk of permuted weights (contiguous float4s) ----
        for (int i = tid; i < OC * 16; i += THREADS) {
            const int oc = i >> 4, q = i & 15;
            ((float4*)wsh)[oc * 16 + q] =
                ((const float4*)(g_wperm + oc * KTOT + kn * 64))[q];
        }
        __syncthreads();

        // ---- GEMM rank-64 update: 4 pixels x 8 ocs, packed f32x2 over k-pairs ----
#pragma unroll
        for (int kq = 0; kq < 16; kq++) {
            ulonglong2 sv[4];
#pragma unroll
            for (int i = 0; i < 4; i++)
                sv[i] = *(const ulonglong2*)&s4[(pg + 16 * i) * SROWQ + (kq ^ pg)];
#pragma unroll
            for (int j = 0; j < 8; j++) {
                const ulonglong2 wv =
                    *(const ulonglong2*)(wsh + (ocg * 8 + j) * 64 + kq * 4);
#pragma unroll
                for (int i = 0; i < 4; i++) {
                    asm("fma.rn.f32x2 %0, %1, %2, %0;"
                        : "+l"(acc2[i][j]) : "l"(sv[i].x), "l"(wv.x));
                    asm("fma.rn.f32x2 %0, %1, %2, %0;"
                        : "+l"(acc2[i][j]) : "l"(sv[i].y), "l"(wv.y));
                }
            }
        }
    }

    // ---- epilogue: reduce (even,odd) partials, write out[n][oc][pix] ----
#pragma unroll
    for (int j = 0; j < 8; j++) {
        const int oc = ocg * 8 + j;
        float* op = out + (((size_t)n * OC + oc) << 14) + pixbase + pg;
#pragma unroll
        for (int i = 0; i < 4; i++) {
            const float2 f = *(const float2*)&acc2[i][j];
            op[16 * i] = f.x + f.y;
        }
    }
}

extern "C" void kernel_launch(void* const* d_in, const int* in_sizes, int n_in,
                              void* d_out, int out_size)
{
    const float* x      = (const float*)d_in[0];   // (4, 64, 128, 128)
    const float* offset = (const float*)d_in[1];   // (4, 18, 128, 128)
    const float* weight = (const float*)d_in[2];   // (64, 64, 9)
    float* out = (float*)d_out;                    // (4, 64, 128, 128)
    (void)in_sizes; (void)n_in; (void)out_size;

    nchw_to_nhwc_kernel<<<4 * 512, 256>>>(x);
    permute_w_kernel<<<(OC * KTOT + 255) / 256, 256>>>(weight);
    dcn_main_kernel<<<4 * 256, THREADS>>>(offset, out);
}

// round 6
// speedup vs baseline: 3.3814x; 1.1184x over previous
#include <cuda_runtime.h>
#include <cstdint>

#define C_IN  64
#define OC    64
#define KNPTS 9
#define PLANE 16384
#define KTOT  576

#define THREADS 256
#define PIXB   128                  // pixels per block (M)
#define NBLK   (4 * PLANE / PIXB)   // 512

// ---- scratch (__device__ globals: allocation is forbidden) ----
__device__ float g_xhwc[(size_t)4 * PLANE * C_IN];   // NHWC x
__device__ float g_whi[KNPTS * OC * C_IN];           // tf32-hi weights [kn][oc][c]
__device__ float g_wlo[KNPTS * OC * C_IN];           // tf32-lo weights

// ---- dynamic smem layout (bytes) ----
#define SM_AHI    0                 // A tile hi: 128 x 64 fp32, XOR-swizzled   (32768)
#define SM_ALO    32768             // A tile lo                                (32768)
#define SM_BHI    65536             // B tile hi: 64 x 64                       (16384)
#define SM_BLO    81920             // B tile lo                                (16384)
#define SM_INTERP 98304             // 1152 x 12B                               (13824)
#define SM_TOTAL  112128
#define CS_STRIDE 132               // epilogue C stage row stride (floats)

// word-index swizzles (conflict-free fragment LDS: bank = 4*row + col permutation)
#define AW(p, c) (((p) << 6) + ((c) ^ (((p) & 7) << 2)))
#define BW(n, k) (((n) << 6) + ((k) ^ (((n) & 7) << 2)))

__device__ __forceinline__ float tf32_rn(float x) {
    uint32_t r;
    asm("cvt.rna.tf32.f32 %0, %1;" : "=r"(r) : "r"(__float_as_uint(x)));
    return __uint_as_float(r);
}

#define MMA(C, a0, a1, a2, a3, b0, b1)                                          \
    asm volatile("mma.sync.aligned.m16n8k8.row.col.f32.tf32.tf32.f32 "          \
                 "{%0,%1,%2,%3},{%4,%5,%6,%7},{%8,%9},{%0,%1,%2,%3};"           \
                 : "+f"(C[0]), "+f"(C[1]), "+f"(C[2]), "+f"(C[3])               \
                 : "r"(a0), "r"(a1), "r"(a2), "r"(a3), "r"(b0), "r"(b1))

// ---------------- NCHW -> NHWC transpose ----------------
__global__ __launch_bounds__(256)
void nchw_to_nhwc_kernel(const float* __restrict__ x)
{
    __shared__ float t[64][33];
    const int n   = blockIdx.x >> 9;
    const int hw0 = (blockIdx.x & 511) << 5;
    const int tid = threadIdx.x;
    const float* xn = x + ((size_t)n << 20);
    for (int idx = tid; idx < 64 * 32; idx += 256) {
        const int c = idx >> 5, i = idx & 31;
        t[c][i] = xn[((size_t)c << 14) + hw0 + i];
    }
    __syncthreads();
    float* dst = g_xhwc + (((size_t)n << 14) + hw0) * 64;
    for (int idx = tid; idx < 64 * 32; idx += 256) {
        const int i = idx >> 6, c = idx & 63;
        dst[(size_t)i * 64 + c] = t[c][i];
    }
}

// ---------------- weight: permute to [kn][oc][c] + tf32 hi/lo split ----------------
__global__ __launch_bounds__(256)
void wsplit_kernel(const float* __restrict__ w)
{
    const int i = blockIdx.x * 256 + threadIdx.x;   // i = kn*4096 + oc*64 + c
    if (i < KNPTS * OC * C_IN) {
        const int kn = i >> 12, r = i & 4095;
        const int oc = r >> 6, c = r & 63;
        const float v  = w[oc * KTOT + c * KNPTS + kn];
        const float hi = tf32_rn(v);
        g_whi[i] = hi;
        g_wlo[i] = tf32_rn(v - hi);
    }
}

// ---------------- main kernel: sample -> 3xTF32 mma.sync GEMM ----------------
struct Interp { short x0, y0; float fx, fy; };

extern __shared__ char smem[];

__global__ __launch_bounds__(THREADS, 2)
void dcn_mma_kernel(const float* __restrict__ offset, float* __restrict__ out)
{
    const int tid  = threadIdx.x;
    const int wid  = tid >> 5;
    const int lane = tid & 31;
    const int n       = blockIdx.x >> 7;            // 128 blocks per image
    const int pixbase = (blockIdx.x & 127) << 7;    // 128 consecutive pixels

    const float* offn = offset + (size_t)n * (KNPTS * 2) * PLANE;
    const float* xb   = g_xhwc + (((size_t)n) << 14) * 64;

    float*    Ahi = (float*)(smem + SM_AHI);
    float*    Alo = (float*)(smem + SM_ALO);
    float*    Bhi = (float*)(smem + SM_BHI);
    float*    Blo = (float*)(smem + SM_BLO);
    const uint32_t* Ahiw = (const uint32_t*)Ahi;
    const uint32_t* Alow = (const uint32_t*)Alo;
    const uint32_t* Bhiw = (const uint32_t*)Bhi;
    const uint32_t* Blow = (const uint32_t*)Blo;
    Interp* interp = (Interp*)(smem + SM_INTERP);

    // ---- Phase 1: interp metadata per (pixel, kernel-point) ----
    for (int it = tid; it < PIXB * KNPTS; it += THREADS) {
        const int p  = it / 9;
        const int kn = it - p * 9;
        const int pix = pixbase + p;
        const int oh = pix >> 7, ow = pix & 127;
        const float iy = (float)oh + offn[(2 * kn)     * PLANE + pix];
        const float ix = (float)ow + offn[(2 * kn + 1) * PLANE + pix];
        const float y0f = floorf(iy), x0f = floorf(ix);
        Interp t; t.x0 = (short)x0f; t.y0 = (short)y0f; t.fx = ix - x0f; t.fy = iy - y0f;
        interp[it] = t;
    }

    const int tg = tid >> 4;        // sampling task group 0..15
    const int lh = tid & 15;        // channel quad owner: channels 4lh..4lh+3

    // GEMM warp tiling: 4 warps along M, 2 along N; warp tile 32x32
    const int m0 = (wid & 3) * 32;
    const int n0 = (wid >> 2) * 32;
    const int r  = lane >> 2;       // fragment row within group (0..7)
    const int u  = lane & 3;        // fragment col within group (0..3)
    const int sw = r << 2;

    float acc[2][4][4];
#pragma unroll
    for (int mt = 0; mt < 2; mt++)
#pragma unroll
        for (int nt = 0; nt < 4; nt++)
#pragma unroll
            for (int q = 0; q < 4; q++) acc[mt][nt][q] = 0.f;

    for (int kn = 0; kn < KNPTS; kn++) {
        __syncthreads();   // prev GEMM reads done (and interp ready on kn==0)

        // ---- sample 128 pixels x 64 ch, tf32 hi/lo split, swizzled STS.128 ----
#pragma unroll
        for (int it = 0; it < 8; it++) {
            const int p = it * 16 + tg;
            const Interp t = interp[p * 9 + kn];
            const int x0 = t.x0, y0 = t.y0, x1 = x0 + 1, y1 = y0 + 1;
            const float wx1 = t.fx, wy1 = t.fy;
            const float wx0 = 1.f - wx1, wy0 = 1.f - wy1;
            const float mx0 = ((unsigned)x0 < 128u) ? 1.f : 0.f;
            const float mx1 = ((unsigned)x1 < 128u) ? 1.f : 0.f;
            const float my0 = ((unsigned)y0 < 128u) ? 1.f : 0.f;
            const float my1 = ((unsigned)y1 < 128u) ? 1.f : 0.f;
            const int cx0 = min(max((int)x0, 0), 127), cx1 = min(max((int)x1, 0), 127);
            const int cy0 = min(max((int)y0, 0), 127), cy1 = min(max((int)y1, 0), 127);
            const float w00 = wx0 * wy0 * mx0 * my0;
            const float w01 = wx1 * wy0 * mx1 * my0;
            const float w10 = wx0 * wy1 * mx0 * my1;
            const float w11 = wx1 * wy1 * mx1 * my1;
            const float4 a = *(const float4*)(xb + (((cy0 << 7) + cx0) << 6) + 4 * lh);
            const float4 b = *(const float4*)(xb + (((cy0 << 7) + cx1) << 6) + 4 * lh);
            const float4 c = *(const float4*)(xb + (((cy1 << 7) + cx0) << 6) + 4 * lh);
            const float4 d = *(const float4*)(xb + (((cy1 << 7) + cx1) << 6) + 4 * lh);
            float v[4];
            v[0] = w00 * a.x + w01 * b.x + w10 * c.x + w11 * d.x;
            v[1] = w00 * a.y + w01 * b.y + w10 * c.y + w11 * d.y;
            v[2] = w00 * a.z + w01 * b.z + w10 * c.z + w11 * d.z;
            v[3] = w00 * a.w + w01 * b.w + w10 * c.w + w11 * d.w;
            float4 hi, lo;
            hi.x = tf32_rn(v[0]); lo.x = tf32_rn(v[0] - hi.x);
            hi.y = tf32_rn(v[1]); lo.y = tf32_rn(v[1] - hi.y);
            hi.z = tf32_rn(v[2]); lo.z = tf32_rn(v[2] - hi.z);
            hi.w = tf32_rn(v[3]); lo.w = tf32_rn(v[3] - hi.w);
            const int wix = AW(p, 4 * lh);          // float4-aligned (low 2 bits intact)
            *(float4*)(Ahi + wix) = hi;
            *(float4*)(Alo + wix) = lo;
        }

        // ---- stage weight chunk [oc][c] hi/lo into swizzled B tiles ----
        for (int i = tid; i < OC * 16; i += THREADS) {
            const int oc = i >> 4, q = i & 15;
            const int wix = BW(oc, 4 * q);
            const int gi  = (kn << 12) + (oc << 6) + 4 * q;
            *(float4*)(Bhi + wix) = *(const float4*)(g_whi + gi);
            *(float4*)(Blo + wix) = *(const float4*)(g_wlo + gi);
        }
        __syncthreads();

        // ---- GEMM: 8 k-steps of m16n8k8, 3xTF32 compensation ----
#pragma unroll
        for (int ks = 0; ks < 8; ks++) {
            const int c0 = ks * 8 + u, c1 = c0 + 4;
            uint32_t ah[2][4], al[2][4];
#pragma unroll
            for (int mt = 0; mt < 2; mt++) {
                const int p0 = m0 + mt * 16 + r, p1 = p0 + 8;
                const int i00 = (p0 << 6) + (c0 ^ sw), i10 = (p1 << 6) + (c0 ^ sw);
                const int i01 = (p0 << 6) + (c1 ^ sw), i11 = (p1 << 6) + (c1 ^ sw);
                ah[mt][0] = Ahiw[i00]; ah[mt][1] = Ahiw[i10];
                ah[mt][2] = Ahiw[i01]; ah[mt][3] = Ahiw[i11];
                al[mt][0] = Alow[i00]; al[mt][1] = Alow[i10];
                al[mt][2] = Alow[i01]; al[mt][3] = Alow[i11];
            }
            uint32_t bh[4][2], bl[4][2];
#pragma unroll
            for (int nt = 0; nt < 4; nt++) {
                const int nn = n0 + nt * 8 + r;
                const int j0 = (nn << 6) + (c0 ^ sw), j1 = (nn << 6) + (c1 ^ sw);
                bh[nt][0] = Bhiw[j0]; bh[nt][1] = Bhiw[j1];
                bl[nt][0] = Blow[j0]; bl[nt][1] = Blow[j1];
            }
#pragma unroll
            for (int mt = 0; mt < 2; mt++)
#pragma unroll
                for (int nt = 0; nt < 4; nt++) {
                    MMA(acc[mt][nt], al[mt][0], al[mt][1], al[mt][2], al[mt][3],
                        bh[nt][0], bh[nt][1]);
                    MMA(acc[mt][nt], ah[mt][0], ah[mt][1], ah[mt][2], ah[mt][3],
                        bl[nt][0], bl[nt][1]);
                    MMA(acc[mt][nt], ah[mt][0], ah[mt][1], ah[mt][2], ah[mt][3],
                        bh[nt][0], bh[nt][1]);
                }
        }
    }

    // ---- epilogue: stage C in smem (oc-major), then coalesced STG ----
    __syncthreads();
    float* Cs = (float*)smem;   // 64 x CS_STRIDE floats (reuses A buffers)
#pragma unroll
    for (int mt = 0; mt < 2; mt++)
#pragma unroll
        for (int nt = 0; nt < 4; nt++) {
            const int p  = m0 + mt * 16 + r;
            const int oc = n0 + nt * 8 + 2 * u;
            Cs[oc * CS_STRIDE + p]            = acc[mt][nt][0];
            Cs[(oc + 1) * CS_STRIDE + p]      = acc[mt][nt][1];
            Cs[oc * CS_STRIDE + p + 8]        = acc[mt][nt][2];
            Cs[(oc + 1) * CS_STRIDE + p + 8]  = acc[mt][nt][3];
        }
    __syncthreads();
    float* ob = out + (((size_t)n * OC) << 14) + pixbase;
#pragma unroll
    for (int k = 0; k < 8; k++) {
        const int idx = tid + k * 256;          // float4 id
        const int oc = idx >> 5, fq = idx & 31; // one warp = one full oc row
        const float4 v = *(const float4*)(Cs + oc * CS_STRIDE + fq * 4);
        *(float4*)(ob + ((size_t)oc << 14) + fq * 4) = v;
    }
}

extern "C" void kernel_launch(void* const* d_in, const int* in_sizes, int n_in,
                              void* d_out, int out_size)
{
    const float* x      = (const float*)d_in[0];   // (4, 64, 128, 128)
    const float* offset = (const float*)d_in[1];   // (4, 18, 128, 128)
    const float* weight = (const float*)d_in[2];   // (64, 64, 9)
    float* out = (float*)d_out;                    // (4, 64, 128, 128)
    (void)in_sizes; (void)n_in; (void)out_size;

    static int smem_set = 0;
    if (!smem_set) {
        cudaFuncSetAttribute(dcn_mma_kernel,
                             cudaFuncAttributeMaxDynamicSharedMemorySize, SM_TOTAL);
        smem_set = 1;
    }
    nchw_to_nhwc_kernel<<<4 * 512, 256>>>(x);
    wsplit_kernel<<<(KNPTS * OC * C_IN + 255) / 256, 256>>>(weight);
    dcn_mma_kernel<<<NBLK, THREADS, SM_TOTAL>>>(offset, out);
}